// round 14
// baseline (speedup 1.0000x reference)
#include <cuda_runtime.h>
#include <cuda_bf16.h>
#include <cstdint>

#define B_  4
#define S_  4096
#define DM  768
#define DK  64
#define NS  8          // KV splits per q-tile
#define NJ  64         // number of 64-row q-tiles per batch
#define PN  192        // proj MMA N (WQ|WK|WV)

// Scratch (device globals: no allocation allowed)
__device__ float  g_Opart[B_ * NS * NJ * 64 * DK];  // unnormalized partial O
__device__ float2 g_ml   [B_ * NS * NJ * 64];       // per-row (m, l) per split
__device__ __nv_bfloat16 g_Wbh[PN * DM];            // W^T hi  [n][k]
__device__ __nv_bfloat16 g_Wbl[PN * DM];            // W^T lo  [n][k]
__device__ __nv_bfloat16 g_Qbh[B_ * S_ * DK];       // Q hi [s][d] (x0.125)
__device__ __nv_bfloat16 g_Qbl[B_ * S_ * DK];       // Q lo
__device__ __nv_bfloat16 g_Kbh[B_ * S_ * DK];       // K hi [s][d]
__device__ __nv_bfloat16 g_Kbl[B_ * S_ * DK];       // K lo
__device__ __nv_bfloat16 g_Vth[B_ * DK * S_];       // V^T hi [d][s]
__device__ __nv_bfloat16 g_Vtl[B_ * DK * S_];       // V^T lo

// ---------------- legacy tensor-core helpers (sm_80 baseline PTX) -----------
__device__ __forceinline__ uint32_t smem_u32(const void* p) {
    uint32_t a;
    asm("{ .reg .u64 t; cvta.to.shared.u64 t, %1; cvt.u32.u64 %0, t; }"
        : "=r"(a) : "l"(p));
    return a;
}
__device__ __forceinline__ void ldm_x4(uint32_t* r, uint32_t addr) {
    asm volatile("ldmatrix.sync.aligned.m8n8.x4.shared.b16 {%0,%1,%2,%3}, [%4];"
                 : "=r"(r[0]), "=r"(r[1]), "=r"(r[2]), "=r"(r[3]) : "r"(addr));
}
__device__ __forceinline__ void mma_bf16(float* d, const uint32_t* a,
                                         uint32_t b0, uint32_t b1) {
    asm volatile("mma.sync.aligned.m16n8k16.row.col.f32.bf16.bf16.f32 "
                 "{%0,%1,%2,%3}, {%4,%5,%6,%7}, {%8,%9}, {%0,%1,%2,%3};"
                 : "+f"(d[0]), "+f"(d[1]), "+f"(d[2]), "+f"(d[3])
                 : "r"(a[0]), "r"(a[1]), "r"(a[2]), "r"(a[3]), "r"(b0), "r"(b1));
}
__device__ __forceinline__ uint32_t bf2u(__nv_bfloat162 v) {
    return *reinterpret_cast<uint32_t*>(&v);
}
__device__ __forceinline__ void split_hl(float x, float y, uint32_t& h, uint32_t& l) {
    __nv_bfloat162 hb = __floats2bfloat162_rn(x, y);
    float2 hf = __bfloat1622float2(hb);
    __nv_bfloat162 lb = __floats2bfloat162_rn(x - hf.x, y - hf.y);
    h = bf2u(hb); l = bf2u(lb);
}

// =====================================================================
// Kernel 0: prep W — transpose + bf16 hi/lo split of [WQ|WK|WV].
// =====================================================================
__global__ __launch_bounds__(256) void prep_w(
    const float* __restrict__ WQ,
    const float* __restrict__ WK,
    const float* __restrict__ WV)
{
    const int n = blockIdx.x;
    const float* W = (n < 64) ? WQ : ((n < 128) ? WK : WV);
    const int col = n & 63;
    const int tid = threadIdx.x;
#pragma unroll
    for (int e = 0; e < 3; e++) {
        const int k = tid * 3 + e;
        float v = W[k * DK + col];
        __nv_bfloat16 h = __float2bfloat16_rn(v);
        __nv_bfloat16 l = __float2bfloat16_rn(v - __bfloat162float(h));
        g_Wbh[n * DM + k] = h;
        g_Wbl[n * DM + k] = l;
    }
}

// =====================================================================
// Kernel 1: QKV projection via mma.sync bf16x3 (fp32 accum).
// grid = 256 (64-row stripes), block = 128 (4 warps x 16 rows).
// 73.7KB smem -> 3 blocks/SM on all 148 SMs (was 1 block/SM).
// Outputs bf16 hi/lo Q,K ([s][d]) and V^T ([d][s]).
// =====================================================================
#define ASM_AH 0
#define ASM_AL (64 * 144)                // 9216
#define ASM_BH (2 * 64 * 144)            // 18432
#define ASM_BL (ASM_BH + PN * 144)       // 46080
#define PSM_TOTAL (ASM_BL + PN * 144)    // 73728

__global__ __launch_bounds__(128) void proj_kernel(const float* __restrict__ x)
{
    extern __shared__ char smraw[];
    const uint32_t smb = smem_u32(smraw);
    const int tid = threadIdx.x;
    const int w = tid >> 5;
    const int lane = tid & 31;
    const int row0 = blockIdx.x * 64;

    float acc[24][4];
#pragma unroll
    for (int nt = 0; nt < 24; nt++)
#pragma unroll
        for (int q = 0; q < 4; q++) acc[nt][q] = 0.0f;

    const uint32_t aOff = (uint32_t)(w * 16 + (lane & 15)) * 144 + (uint32_t)((lane >> 4) * 16);
    const uint32_t bRow = (uint32_t)((lane & 7) | ((lane & 16) >> 1));
    const uint32_t bKo  = (uint32_t)(((lane >> 3) & 1) * 16);

    for (int kc = 0; kc < DM / 64; kc++) {
        const int k0 = kc * 64;
        __syncthreads();

        // A chunk: x[row0..+63][k0..+63] -> bf16 hi/lo
#pragma unroll
        for (int i = 0; i < 4; i++) {
            const int item = i * 128 + tid;       // 512 items: 64 rows x 8 groups
            const int r = item >> 3, gp = item & 7;
            const float* src = &x[(row0 + r) * DM + k0 + gp * 8];
            float4 a = *reinterpret_cast<const float4*>(src);
            float4 b = *reinterpret_cast<const float4*>(src + 4);
            uint4 hv, lv;
            split_hl(a.x, a.y, hv.x, lv.x);
            split_hl(a.z, a.w, hv.y, lv.y);
            split_hl(b.x, b.y, hv.z, lv.z);
            split_hl(b.z, b.w, hv.w, lv.w);
            const uint32_t off = (uint32_t)(r * 144 + gp * 16);
            *reinterpret_cast<uint4*>(smraw + ASM_AH + off) = hv;
            *reinterpret_cast<uint4*>(smraw + ASM_AL + off) = lv;
        }
        // B chunk copy from pre-split g_Wb*
#pragma unroll
        for (int i = 0; i < 12; i++) {
            const int item = i * 128 + tid;       // 1536 items: 192 rows x 8 groups
            const int n = item >> 3, gp = item & 7;
            uint4 hv = *reinterpret_cast<const uint4*>(&g_Wbh[n * DM + k0 + gp * 8]);
            uint4 lv = *reinterpret_cast<const uint4*>(&g_Wbl[n * DM + k0 + gp * 8]);
            const uint32_t off = (uint32_t)(n * 144 + gp * 16);
            *reinterpret_cast<uint4*>(smraw + ASM_BH + off) = hv;
            *reinterpret_cast<uint4*>(smraw + ASM_BL + off) = lv;
        }
        __syncthreads();

#pragma unroll
        for (int ks = 0; ks < 4; ks++) {
            uint32_t ah[4], al[4];
            ldm_x4(ah, smb + ASM_AH + aOff + ks * 32);
            ldm_x4(al, smb + ASM_AL + aOff + ks * 32);
#pragma unroll
            for (int np = 0; np < 12; np++) {
                const uint32_t bo = (uint32_t)(np * 16 + bRow) * 144 + bKo + ks * 32;
                uint32_t bh[4], bl[4];
                ldm_x4(bh, smb + ASM_BH + bo);
                ldm_x4(bl, smb + ASM_BL + bo);
                mma_bf16(acc[2 * np],     ah, bh[0], bh[1]);
                mma_bf16(acc[2 * np + 1], ah, bh[2], bh[3]);
                mma_bf16(acc[2 * np],     ah, bl[0], bl[1]);
                mma_bf16(acc[2 * np + 1], ah, bl[2], bl[3]);
                mma_bf16(acc[2 * np],     al, bh[0], bh[1]);
                mma_bf16(acc[2 * np + 1], al, bh[2], bh[3]);
            }
        }
    }

    // Epilogue. C-frag: (row g, cols c2,c2+1) = d0,d1; row g+8 = d2,d3.
    const int g = lane >> 2;
    const int c2 = (lane & 3) * 2;
    const int r0g = row0 + w * 16 + g;
#pragma unroll
    for (int nt = 0; nt < 8; nt++) {
        const int col = nt * 8 + c2;
        uint32_t h, l;
        split_hl(acc[nt][0] * 0.125f, acc[nt][1] * 0.125f, h, l);
        *reinterpret_cast<uint32_t*>(&g_Qbh[r0g * DK + col]) = h;
        *reinterpret_cast<uint32_t*>(&g_Qbl[r0g * DK + col]) = l;
        split_hl(acc[nt][2] * 0.125f, acc[nt][3] * 0.125f, h, l);
        *reinterpret_cast<uint32_t*>(&g_Qbh[(r0g + 8) * DK + col]) = h;
        *reinterpret_cast<uint32_t*>(&g_Qbl[(r0g + 8) * DK + col]) = l;
        split_hl(acc[nt + 8][0], acc[nt + 8][1], h, l);
        *reinterpret_cast<uint32_t*>(&g_Kbh[r0g * DK + col]) = h;
        *reinterpret_cast<uint32_t*>(&g_Kbl[r0g * DK + col]) = l;
        split_hl(acc[nt + 8][2], acc[nt + 8][3], h, l);
        *reinterpret_cast<uint32_t*>(&g_Kbh[(r0g + 8) * DK + col]) = h;
        *reinterpret_cast<uint32_t*>(&g_Kbl[(r0g + 8) * DK + col]) = l;
    }

    // V: stage fp32 [64 d][72 s] in SMEM (overlays A), then bf16 hi/lo to g_Vt*
    __syncthreads();
    float* stage = reinterpret_cast<float*>(smraw);   // 64*72*4 = 18432 B
    const int srow = w * 16 + g;
#pragma unroll
    for (int nt = 16; nt < 24; nt++) {
        const int d = (nt - 16) * 8 + c2;
        stage[d * 72 + srow]           = acc[nt][0];
        stage[(d + 1) * 72 + srow]     = acc[nt][1];
        stage[d * 72 + srow + 8]       = acc[nt][2];
        stage[(d + 1) * 72 + srow + 8] = acc[nt][3];
    }
    __syncthreads();
    const int bb = row0 >> 12;
    const int s0 = row0 & (S_ - 1);
#pragma unroll
    for (int i = 0; i < 8; i++) {
        const int item = i * 128 + tid;   // 1024 items: 64 d x 16 float4 (full 64 s)
        const int d = item >> 4, s4 = item & 15;
        float4 v = *reinterpret_cast<const float4*>(&stage[d * 72 + s4 * 4]);
        uint2 hv, lv;
        split_hl(v.x, v.y, hv.x, lv.x);
        split_hl(v.z, v.w, hv.y, lv.y);
        const int idx = (bb * DK + d) * S_ + s0 + s4 * 4;
        *reinterpret_cast<uint2*>(&g_Vth[idx]) = hv;
        *reinterpret_cast<uint2*>(&g_Vtl[idx]) = lv;
    }
}

// =====================================================================
// Kernel 2: split-KV causal flash attention via mma.sync bf16x3.
// grid = (NJ, 4, NS), block = 128 (4 warps). Q fragments are HOISTED
// into registers before the KV loop (staged once through the K SMEM
// region). SMEM = K+V hi/lo only = 36.9KB.
// =====================================================================
#define ATS 144
#define AKH 0
#define AKL (64 * ATS)
#define AVH (2 * 64 * ATS)
#define AVL (3 * 64 * ATS)
#define ATTN_SMEM (4 * 64 * ATS)    // 36864

__global__ __launch_bounds__(128, 4) void attn_kernel()
{
    extern __shared__ char smraw[];
    const uint32_t smb = smem_u32(smraw);
    const int tid = threadIdx.x;
    const int w = tid >> 5;
    const int lane = tid & 31;
    const int g = lane >> 2;
    const int qd = lane & 3;
    const int b = blockIdx.y;
    const int j = blockIdx.x;
    const int split = blockIdx.z;
    const int q0 = j * 64;
    const int nkv = j + 1;
    const int per = (nkv + NS - 1) / NS;
    const int t0 = split * per;
    const int t1 = min(nkv, t0 + per);
    if (t0 >= t1) return;

    const uint32_t aOff = (uint32_t)(w * 16 + (lane & 15)) * ATS + (uint32_t)((lane >> 4) * 16);
    const uint32_t bRow = (uint32_t)((lane & 7) | ((lane & 16) >> 1));
    const uint32_t bKo  = (uint32_t)(((lane >> 3) & 1) * 16);

    // Stage Q (64x64 bf16 hi/lo) through the K region, hoist frags to regs
#pragma unroll
    for (int i = 0; i < 4; i++) {
        const int item = i * 128 + tid;   // 512 items: 64 rows x 8 groups
        const int r = item >> 3, gp = item & 7;
        const int src = (b * S_ + q0 + r) * DK + gp * 8;
        const uint32_t off = (uint32_t)(r * ATS + gp * 16);
        *reinterpret_cast<uint4*>(smraw + AKH + off) =
            *reinterpret_cast<const uint4*>(&g_Qbh[src]);
        *reinterpret_cast<uint4*>(smraw + AKL + off) =
            *reinterpret_cast<const uint4*>(&g_Qbl[src]);
    }
    __syncthreads();
    uint32_t qh[4][4], ql[4][4];
#pragma unroll
    for (int kc = 0; kc < 4; kc++) {
        ldm_x4(qh[kc], smb + AKH + aOff + kc * 32);
        ldm_x4(ql[kc], smb + AKL + aOff + kc * 32);
    }

    float o[8][4];
#pragma unroll
    for (int nt = 0; nt < 8; nt++)
#pragma unroll
        for (int c = 0; c < 4; c++) o[nt][c] = 0.0f;
    float m0 = -1e30f, m1 = -1e30f, l0 = 0.0f, l1 = 0.0f;

    for (int t = t0; t < t1; t++) {
        const int k0 = t * 64;
        __syncthreads();   // previous ldmatrix reads done (incl. Q frag loads on t0)

        // Load K [key][d] and V^T [d][s] bf16 hi/lo tiles
#pragma unroll
        for (int i = 0; i < 4; i++) {
            const int item = i * 128 + tid;
            const int r = item >> 3, gp = item & 7;
            const uint32_t off = (uint32_t)(r * ATS + gp * 16);
            const int ksrc = (b * S_ + k0 + r) * DK + gp * 8;
            const int vsrc = (b * DK + r) * S_ + k0 + gp * 8;
            *reinterpret_cast<uint4*>(smraw + AKH + off) =
                *reinterpret_cast<const uint4*>(&g_Kbh[ksrc]);
            *reinterpret_cast<uint4*>(smraw + AKL + off) =
                *reinterpret_cast<const uint4*>(&g_Kbl[ksrc]);
            *reinterpret_cast<uint4*>(smraw + AVH + off) =
                *reinterpret_cast<const uint4*>(&g_Vth[vsrc]);
            *reinterpret_cast<uint4*>(smraw + AVL + off) =
                *reinterpret_cast<const uint4*>(&g_Vtl[vsrc]);
        }
        __syncthreads();

        // GEMM1: S = Q @ K^T (bf16x3), Q frags from registers
        float s[8][4];
#pragma unroll
        for (int nt = 0; nt < 8; nt++)
#pragma unroll
            for (int c = 0; c < 4; c++) s[nt][c] = 0.0f;
#pragma unroll
        for (int kc = 0; kc < 4; kc++) {
#pragma unroll
            for (int np = 0; np < 4; np++) {
                const uint32_t bo = (uint32_t)(np * 16 + bRow) * ATS + bKo + kc * 32;
                uint32_t kh[4], kl[4];
                ldm_x4(kh, smb + AKH + bo);
                ldm_x4(kl, smb + AKL + bo);
                mma_bf16(s[2 * np],     qh[kc], kh[0], kh[1]);
                mma_bf16(s[2 * np + 1], qh[kc], kh[2], kh[3]);
                mma_bf16(s[2 * np],     qh[kc], kl[0], kl[1]);
                mma_bf16(s[2 * np + 1], qh[kc], kl[2], kl[3]);
                mma_bf16(s[2 * np],     ql[kc], kh[0], kh[1]);
                mma_bf16(s[2 * np + 1], ql[kc], kh[2], kh[3]);
            }
        }

        // Online softmax + P hi/lo pack (registers only)
        const bool maskt = (t == nkv - 1);
        uint32_t ph0[8], pl0[8], ph1[8], pl1[8];
        {   // row 0 (g): c0, c1
            const int qrow = q0 + w * 16 + g;
            if (maskt) {
#pragma unroll
                for (int nt = 0; nt < 8; nt++) {
                    const int key = k0 + nt * 8 + 2 * qd;
                    if (key > qrow)     s[nt][0] = -1e30f;
                    if (key + 1 > qrow) s[nt][1] = -1e30f;
                }
            }
            float mi = -1e30f;
#pragma unroll
            for (int nt = 0; nt < 8; nt++)
                mi = fmaxf(mi, fmaxf(s[nt][0], s[nt][1]));
            mi = fmaxf(mi, __shfl_xor_sync(0xffffffffu, mi, 1));
            mi = fmaxf(mi, __shfl_xor_sync(0xffffffffu, mi, 2));
            const float mnew = fmaxf(m0, mi);
            const float alpha = __expf(m0 - mnew);
            float rs = 0.0f;
#pragma unroll
            for (int nt = 0; nt < 8; nt++) {
                float p0 = __expf(s[nt][0] - mnew);
                float p1 = __expf(s[nt][1] - mnew);
                rs += p0 + p1;
                split_hl(p0, p1, ph0[nt], pl0[nt]);
                o[nt][0] *= alpha; o[nt][1] *= alpha;
            }
            rs += __shfl_xor_sync(0xffffffffu, rs, 1);
            rs += __shfl_xor_sync(0xffffffffu, rs, 2);
            l0 = l0 * alpha + rs;
            m0 = mnew;
        }
        {   // row 1 (g+8): c2, c3
            const int qrow = q0 + w * 16 + g + 8;
            if (maskt) {
#pragma unroll
                for (int nt = 0; nt < 8; nt++) {
                    const int key = k0 + nt * 8 + 2 * qd;
                    if (key > qrow)     s[nt][2] = -1e30f;
                    if (key + 1 > qrow) s[nt][3] = -1e30f;
                }
            }
            float mi = -1e30f;
#pragma unroll
            for (int nt = 0; nt < 8; nt++)
                mi = fmaxf(mi, fmaxf(s[nt][2], s[nt][3]));
            mi = fmaxf(mi, __shfl_xor_sync(0xffffffffu, mi, 1));
            mi = fmaxf(mi, __shfl_xor_sync(0xffffffffu, mi, 2));
            const float mnew = fmaxf(m1, mi);
            const float alpha = __expf(m1 - mnew);
            float rs = 0.0f;
#pragma unroll
            for (int nt = 0; nt < 8; nt++) {
                float p0 = __expf(s[nt][2] - mnew);
                float p1 = __expf(s[nt][3] - mnew);
                rs += p0 + p1;
                split_hl(p0, p1, ph1[nt], pl1[nt]);
                o[nt][2] *= alpha; o[nt][3] *= alpha;
            }
            rs += __shfl_xor_sync(0xffffffffu, rs, 1);
            rs += __shfl_xor_sync(0xffffffffu, rs, 2);
            l1 = l1 * alpha + rs;
            m1 = mnew;
        }

        // GEMM2: O += P @ V^T (bf16x3); A-frags direct from P registers
#pragma unroll
        for (int kc = 0; kc < 4; kc++) {
            uint32_t aH[4] = { ph0[2 * kc], ph1[2 * kc], ph0[2 * kc + 1], ph1[2 * kc + 1] };
            uint32_t aL[4] = { pl0[2 * kc], pl1[2 * kc], pl0[2 * kc + 1], pl1[2 * kc + 1] };
#pragma unroll
            for (int np = 0; np < 4; np++) {
                const uint32_t bo = (uint32_t)(np * 16 + bRow) * ATS + bKo + kc * 32;
                uint32_t vh[4], vl[4];
                ldm_x4(vh, smb + AVH + bo);
                ldm_x4(vl, smb + AVL + bo);
                mma_bf16(o[2 * np],     aH, vh[0], vh[1]);
                mma_bf16(o[2 * np + 1], aH, vh[2], vh[3]);
                mma_bf16(o[2 * np],     aH, vl[0], vl[1]);
                mma_bf16(o[2 * np + 1], aH, vl[2], vl[3]);
                mma_bf16(o[2 * np],     aL, vh[0], vh[1]);
                mma_bf16(o[2 * np + 1], aL, vh[2], vh[3]);
            }
        }
    }

    // Epilogue: write UNNORMALIZED partial O + (m, l)
    const int base = ((b * NS + split) * NJ + j) * 64;
    const int row0 = w * 16 + g;
    const int row1 = row0 + 8;
#pragma unroll
    for (int nt = 0; nt < 8; nt++) {
        const int col = nt * 8 + 2 * qd;
        *reinterpret_cast<float2*>(&g_Opart[(base + row0) * DK + col]) =
            make_float2(o[nt][0], o[nt][1]);
        *reinterpret_cast<float2*>(&g_Opart[(base + row1) * DK + col]) =
            make_float2(o[nt][2], o[nt][3]);
    }
    if (qd == 0) {
        g_ml[base + row0] = make_float2(m0, l0);
        g_ml[base + row1] = make_float2(m1, l1);
    }
}

// =====================================================================
// Kernel 3: combine partials. grid = (NJ, 4), block = 256.
// =====================================================================
__global__ __launch_bounds__(256) void combine_kernel(float* __restrict__ out)
{
    const int j = blockIdx.x, b = blockIdx.y;
    const int tid = threadIdx.x;
    const int r = tid >> 2;
    const int c0 = (tid & 3) * 16;
    const int nkv = j + 1;
    const int per = (nkv + NS - 1) / NS;
    const int nsp = (nkv + per - 1) / per;

    float mv[NS], lv[NS];
    float M = -1e30f;
    for (int s = 0; s < nsp; s++) {
        float2 ml = g_ml[((b * NS + s) * NJ + j) * 64 + r];
        mv[s] = ml.x; lv[s] = ml.y;
        M = fmaxf(M, mv[s]);
    }
    float L = 0.0f, ww[NS];
    for (int s = 0; s < nsp; s++) {
        ww[s] = __expf(mv[s] - M);
        L += ww[s] * lv[s];
    }
    const float inv = 1.0f / L;

    float4 acc[4];
#pragma unroll
    for (int q = 0; q < 4; q++) acc[q] = make_float4(0.f, 0.f, 0.f, 0.f);

    for (int s = 0; s < nsp; s++) {
        const float* Op = &g_Opart[(((b * NS + s) * NJ + j) * 64 + r) * DK + c0];
        const float ws = ww[s];
#pragma unroll
        for (int q = 0; q < 4; q++) {
            float4 v = *reinterpret_cast<const float4*>(Op + q * 4);
            acc[q].x += ws * v.x; acc[q].y += ws * v.y;
            acc[q].z += ws * v.z; acc[q].w += ws * v.w;
        }
    }

    float* op = &out[((b * S_) + j * 64 + r) * DK + c0];
#pragma unroll
    for (int q = 0; q < 4; q++) {
        float4 v = make_float4(acc[q].x * inv, acc[q].y * inv,
                               acc[q].z * inv, acc[q].w * inv);
        *reinterpret_cast<float4*>(op + q * 4) = v;
    }
}

// =====================================================================
extern "C" void kernel_launch(void* const* d_in, const int* in_sizes, int n_in,
                              void* d_out, int out_size)
{
    const float* x  = (const float*)d_in[0];
    const float* WQ = (const float*)d_in[1];
    const float* WK = (const float*)d_in[2];
    const float* WV = (const float*)d_in[3];
    float* out = (float*)d_out;

    (void)in_sizes; (void)n_in; (void)out_size;

    cudaFuncSetAttribute(proj_kernel, cudaFuncAttributeMaxDynamicSharedMemorySize, PSM_TOTAL);
    cudaFuncSetAttribute(attn_kernel, cudaFuncAttributeMaxDynamicSharedMemorySize, ATTN_SMEM);

    prep_w<<<PN, 256>>>(WQ, WK, WV);
    proj_kernel<<<256, 128, PSM_TOTAL>>>(x);
    attn_kernel<<<dim3(NJ, 4, NS), 128, ATTN_SMEM>>>();
    combine_kernel<<<dim3(NJ, 4), 256>>>(out);
}

// round 15
// speedup vs baseline: 1.0618x; 1.0618x over previous
#include <cuda_runtime.h>
#include <cuda_bf16.h>
#include <cstdint>

#define B_  4
#define S_  4096
#define DM  768
#define DK  64
#define NS  8          // KV splits per q-tile
#define NJ  64         // number of 64-row q-tiles per batch
#define PN  192        // proj MMA N (WQ|WK|WV)

// Scratch (device globals: no allocation allowed)
__device__ float  g_Opart[B_ * NS * NJ * 64 * DK];  // unnormalized partial O
__device__ float2 g_ml   [B_ * NS * NJ * 64];       // per-row (m, l) per split
__device__ __nv_bfloat16 g_Wbh[PN * DM];            // W^T hi  [n][k]
__device__ __nv_bfloat16 g_Wbl[PN * DM];            // W^T lo  [n][k]
__device__ __nv_bfloat16 g_Qbh[B_ * S_ * DK];       // Q hi [s][d] (x0.125)
__device__ __nv_bfloat16 g_Qbl[B_ * S_ * DK];       // Q lo
__device__ __nv_bfloat16 g_Kbh[B_ * S_ * DK];       // K hi [s][d]
__device__ __nv_bfloat16 g_Kbl[B_ * S_ * DK];       // K lo
__device__ __nv_bfloat16 g_Vth[B_ * DK * S_];       // V^T hi [d][s]
__device__ __nv_bfloat16 g_Vtl[B_ * DK * S_];       // V^T lo

// ---------------- legacy tensor-core / async-copy helpers (sm_80 PTX) -------
__device__ __forceinline__ uint32_t smem_u32(const void* p) {
    uint32_t a;
    asm("{ .reg .u64 t; cvta.to.shared.u64 t, %1; cvt.u32.u64 %0, t; }"
        : "=r"(a) : "l"(p));
    return a;
}
__device__ __forceinline__ void ldm_x4(uint32_t* r, uint32_t addr) {
    asm volatile("ldmatrix.sync.aligned.m8n8.x4.shared.b16 {%0,%1,%2,%3}, [%4];"
                 : "=r"(r[0]), "=r"(r[1]), "=r"(r[2]), "=r"(r[3]) : "r"(addr));
}
__device__ __forceinline__ void mma_bf16(float* d, const uint32_t* a,
                                         uint32_t b0, uint32_t b1) {
    asm volatile("mma.sync.aligned.m16n8k16.row.col.f32.bf16.bf16.f32 "
                 "{%0,%1,%2,%3}, {%4,%5,%6,%7}, {%8,%9}, {%0,%1,%2,%3};"
                 : "+f"(d[0]), "+f"(d[1]), "+f"(d[2]), "+f"(d[3])
                 : "r"(a[0]), "r"(a[1]), "r"(a[2]), "r"(a[3]), "r"(b0), "r"(b1));
}
__device__ __forceinline__ void cp16(uint32_t dst, const void* src) {
    asm volatile("cp.async.cg.shared.global [%0], [%1], 16;"
                 :: "r"(dst), "l"(src) : "memory");
}
#define CP_COMMIT() asm volatile("cp.async.commit_group;" ::: "memory")
#define CP_WAIT1()  asm volatile("cp.async.wait_group 1;" ::: "memory")
#define CP_WAIT0()  asm volatile("cp.async.wait_group 0;" ::: "memory")

__device__ __forceinline__ uint32_t bf2u(__nv_bfloat162 v) {
    return *reinterpret_cast<uint32_t*>(&v);
}
__device__ __forceinline__ void split_hl(float x, float y, uint32_t& h, uint32_t& l) {
    __nv_bfloat162 hb = __floats2bfloat162_rn(x, y);
    float2 hf = __bfloat1622float2(hb);
    __nv_bfloat162 lb = __floats2bfloat162_rn(x - hf.x, y - hf.y);
    h = bf2u(hb); l = bf2u(lb);
}

// =====================================================================
// Kernel 0: prep W — transpose + bf16 hi/lo split of [WQ|WK|WV].
// =====================================================================
__global__ __launch_bounds__(256) void prep_w(
    const float* __restrict__ WQ,
    const float* __restrict__ WK,
    const float* __restrict__ WV)
{
    const int n = blockIdx.x;
    const float* W = (n < 64) ? WQ : ((n < 128) ? WK : WV);
    const int col = n & 63;
    const int tid = threadIdx.x;
#pragma unroll
    for (int e = 0; e < 3; e++) {
        const int k = tid * 3 + e;
        float v = W[k * DK + col];
        __nv_bfloat16 h = __float2bfloat16_rn(v);
        __nv_bfloat16 l = __float2bfloat16_rn(v - __bfloat162float(h));
        g_Wbh[n * DM + k] = h;
        g_Wbl[n * DM + k] = l;
    }
}

// =====================================================================
// Kernel 1: QKV projection via mma.sync bf16x3 (fp32 accum). (R13 winner)
// grid = 128, block = 256 (8 warps). Outputs bf16 hi/lo Q,K ([s][d])
// and V^T ([d][s]).
// =====================================================================
#define ASM_AH 0
#define ASM_AL (128 * 144)               // 18432
#define ASM_BH (2 * 128 * 144)           // 36864
#define ASM_BL (ASM_BH + PN * 144)       // 64512
#define PSM_TOTAL (ASM_BL + PN * 144)    // 92160

__global__ __launch_bounds__(256, 1) void proj_kernel(const float* __restrict__ x)
{
    extern __shared__ char smraw[];
    const uint32_t smb = smem_u32(smraw);
    const int tid = threadIdx.x;
    const int w = tid >> 5;
    const int lane = tid & 31;
    const int row0 = blockIdx.x * 128;

    float acc[24][4];
#pragma unroll
    for (int nt = 0; nt < 24; nt++)
#pragma unroll
        for (int q = 0; q < 4; q++) acc[nt][q] = 0.0f;

    const uint32_t aOff = (uint32_t)(w * 16 + (lane & 15)) * 144 + (uint32_t)((lane >> 4) * 16);
    const uint32_t bRow = (uint32_t)((lane & 7) | ((lane & 16) >> 1));
    const uint32_t bKo  = (uint32_t)(((lane >> 3) & 1) * 16);

    for (int kc = 0; kc < DM / 64; kc++) {
        const int k0 = kc * 64;
        __syncthreads();

#pragma unroll
        for (int i = 0; i < 4; i++) {
            const int item = i * 256 + tid;
            const int r = item >> 3, gp = item & 7;
            const float* src = &x[(row0 + r) * DM + k0 + gp * 8];
            float4 a = *reinterpret_cast<const float4*>(src);
            float4 b = *reinterpret_cast<const float4*>(src + 4);
            uint4 hv, lv;
            split_hl(a.x, a.y, hv.x, lv.x);
            split_hl(a.z, a.w, hv.y, lv.y);
            split_hl(b.x, b.y, hv.z, lv.z);
            split_hl(b.z, b.w, hv.w, lv.w);
            const uint32_t off = (uint32_t)(r * 144 + gp * 16);
            *reinterpret_cast<uint4*>(smraw + ASM_AH + off) = hv;
            *reinterpret_cast<uint4*>(smraw + ASM_AL + off) = lv;
        }
#pragma unroll
        for (int i = 0; i < 6; i++) {
            const int item = i * 256 + tid;
            const int n = item >> 3, gp = item & 7;
            uint4 hv = *reinterpret_cast<const uint4*>(&g_Wbh[n * DM + k0 + gp * 8]);
            uint4 lv = *reinterpret_cast<const uint4*>(&g_Wbl[n * DM + k0 + gp * 8]);
            const uint32_t off = (uint32_t)(n * 144 + gp * 16);
            *reinterpret_cast<uint4*>(smraw + ASM_BH + off) = hv;
            *reinterpret_cast<uint4*>(smraw + ASM_BL + off) = lv;
        }
        __syncthreads();

#pragma unroll
        for (int ks = 0; ks < 4; ks++) {
            uint32_t ah[4], al[4];
            ldm_x4(ah, smb + ASM_AH + aOff + ks * 32);
            ldm_x4(al, smb + ASM_AL + aOff + ks * 32);
#pragma unroll
            for (int np = 0; np < 12; np++) {
                const uint32_t bo = (uint32_t)(np * 16 + bRow) * 144 + bKo + ks * 32;
                uint32_t bh[4], bl[4];
                ldm_x4(bh, smb + ASM_BH + bo);
                ldm_x4(bl, smb + ASM_BL + bo);
                mma_bf16(acc[2 * np],     ah, bh[0], bh[1]);
                mma_bf16(acc[2 * np + 1], ah, bh[2], bh[3]);
                mma_bf16(acc[2 * np],     ah, bl[0], bl[1]);
                mma_bf16(acc[2 * np + 1], ah, bl[2], bl[3]);
                mma_bf16(acc[2 * np],     al, bh[0], bh[1]);
                mma_bf16(acc[2 * np + 1], al, bh[2], bh[3]);
            }
        }
    }

    // Epilogue. C-frag: (row g, cols c2,c2+1) = d0,d1; row g+8 = d2,d3.
    const int g = lane >> 2;
    const int c2 = (lane & 3) * 2;
    const int r0g = row0 + w * 16 + g;
#pragma unroll
    for (int nt = 0; nt < 8; nt++) {
        const int col = nt * 8 + c2;
        uint32_t h, l;
        split_hl(acc[nt][0] * 0.125f, acc[nt][1] * 0.125f, h, l);
        *reinterpret_cast<uint32_t*>(&g_Qbh[r0g * DK + col]) = h;
        *reinterpret_cast<uint32_t*>(&g_Qbl[r0g * DK + col]) = l;
        split_hl(acc[nt][2] * 0.125f, acc[nt][3] * 0.125f, h, l);
        *reinterpret_cast<uint32_t*>(&g_Qbh[(r0g + 8) * DK + col]) = h;
        *reinterpret_cast<uint32_t*>(&g_Qbl[(r0g + 8) * DK + col]) = l;
        split_hl(acc[nt + 8][0], acc[nt + 8][1], h, l);
        *reinterpret_cast<uint32_t*>(&g_Kbh[r0g * DK + col]) = h;
        *reinterpret_cast<uint32_t*>(&g_Kbl[r0g * DK + col]) = l;
        split_hl(acc[nt + 8][2], acc[nt + 8][3], h, l);
        *reinterpret_cast<uint32_t*>(&g_Kbh[(r0g + 8) * DK + col]) = h;
        *reinterpret_cast<uint32_t*>(&g_Kbl[(r0g + 8) * DK + col]) = l;
    }

    // V: stage fp32 [d][s] in SMEM (overlays A/B), then bf16 hi/lo to g_Vt*
    __syncthreads();
    float* stage = reinterpret_cast<float*>(smraw);   // [64][136] = 34816 B
    const int srow = w * 16 + g;
#pragma unroll
    for (int nt = 16; nt < 24; nt++) {
        const int d = (nt - 16) * 8 + c2;
        stage[d * 136 + srow]           = acc[nt][0];
        stage[(d + 1) * 136 + srow]     = acc[nt][1];
        stage[d * 136 + srow + 8]       = acc[nt][2];
        stage[(d + 1) * 136 + srow + 8] = acc[nt][3];
    }
    __syncthreads();
    const int bb = row0 >> 12;
    const int s0 = row0 & (S_ - 1);
#pragma unroll
    for (int i = 0; i < 8; i++) {
        const int item = i * 256 + tid;   // 2048 items: 64 d x 32 float4
        const int d = item >> 5, s4 = item & 31;
        float4 v = *reinterpret_cast<const float4*>(&stage[d * 136 + s4 * 4]);
        uint2 hv, lv;
        split_hl(v.x, v.y, hv.x, lv.x);
        split_hl(v.z, v.w, hv.y, lv.y);
        const int idx = (bb * DK + d) * S_ + s0 + s4 * 4;
        *reinterpret_cast<uint2*>(&g_Vth[idx]) = hv;
        *reinterpret_cast<uint2*>(&g_Vtl[idx]) = lv;
    }
}

// =====================================================================
// Kernel 2: split-KV causal flash attention, mma.sync bf16x3, cp.async
// DOUBLE-BUFFERED K/V pipeline. grid = (NJ, 4, NS), block = 128 (4 warps).
// Q frags hoisted to regs (staged once through buffer 0). SMEM = 2 stages
// x (KH,KL,VH,VL) x 9216B = 73.7KB -> 3 blocks/SM.
// =====================================================================
#define ATS 144
#define STAGE_BYTES (4 * 64 * ATS)       // 36864 per stage
#define RKH 0
#define RKL (64 * ATS)
#define RVH (2 * 64 * ATS)
#define RVL (3 * 64 * ATS)
#define ATTN_SMEM (2 * STAGE_BYTES)      // 73728

__device__ __forceinline__ void prefetch_kv(uint32_t base, int b, int k0, int tid)
{
#pragma unroll
    for (int i = 0; i < 4; i++) {
        const int item = i * 128 + tid;   // 512 items: 64 rows x 8 groups
        const int r = item >> 3, gp = item & 7;
        const uint32_t off = (uint32_t)(r * ATS + gp * 16);
        const int ksrc = (b * S_ + k0 + r) * DK + gp * 8;
        const int vsrc = (b * DK + r) * S_ + k0 + gp * 8;
        cp16(base + RKH + off, &g_Kbh[ksrc]);
        cp16(base + RKL + off, &g_Kbl[ksrc]);
        cp16(base + RVH + off, &g_Vth[vsrc]);
        cp16(base + RVL + off, &g_Vtl[vsrc]);
    }
}

__global__ __launch_bounds__(128, 3) void attn_kernel()
{
    extern __shared__ char smraw[];
    const uint32_t smb = smem_u32(smraw);
    const int tid = threadIdx.x;
    const int w = tid >> 5;
    const int lane = tid & 31;
    const int g = lane >> 2;
    const int qd = lane & 3;
    const int b = blockIdx.y;
    const int j = blockIdx.x;
    const int split = blockIdx.z;
    const int q0 = j * 64;
    const int nkv = j + 1;
    const int per = (nkv + NS - 1) / NS;
    const int t0 = split * per;
    const int t1 = min(nkv, t0 + per);
    if (t0 >= t1) return;

    const uint32_t aOff = (uint32_t)(w * 16 + (lane & 15)) * ATS + (uint32_t)((lane >> 4) * 16);
    const uint32_t bRow = (uint32_t)((lane & 7) | ((lane & 16) >> 1));
    const uint32_t bKo  = (uint32_t)(((lane >> 3) & 1) * 16);

    // Stage Q (64x64 bf16 hi/lo) through stage-0 K regions, hoist frags to regs
#pragma unroll
    for (int i = 0; i < 4; i++) {
        const int item = i * 128 + tid;
        const int r = item >> 3, gp = item & 7;
        const int src = (b * S_ + q0 + r) * DK + gp * 8;
        const uint32_t off = (uint32_t)(r * ATS + gp * 16);
        *reinterpret_cast<uint4*>(smraw + RKH + off) =
            *reinterpret_cast<const uint4*>(&g_Qbh[src]);
        *reinterpret_cast<uint4*>(smraw + RKL + off) =
            *reinterpret_cast<const uint4*>(&g_Qbl[src]);
    }
    __syncthreads();
    uint32_t qh[4][4], ql[4][4];
#pragma unroll
    for (int kc = 0; kc < 4; kc++) {
        ldm_x4(qh[kc], smb + RKH + aOff + kc * 32);
        ldm_x4(ql[kc], smb + RKL + aOff + kc * 32);
    }
    __syncthreads();   // Q frag loads complete before cp.async overwrites stage 0

    // Prologue prefetch: tile t0 -> stage 0
    prefetch_kv(smb, b, t0 * 64, tid);
    CP_COMMIT();

    float o[8][4];
#pragma unroll
    for (int nt = 0; nt < 8; nt++)
#pragma unroll
        for (int c = 0; c < 4; c++) o[nt][c] = 0.0f;
    float m0 = -1e30f, m1 = -1e30f, l0 = 0.0f, l1 = 0.0f;

    for (int t = t0; t < t1; t++) {
        const int k0 = t * 64;
        const uint32_t cbase = smb + (uint32_t)(((t - t0) & 1) * STAGE_BYTES);

        if (t + 1 < t1) {
            prefetch_kv(smb + (uint32_t)(((t + 1 - t0) & 1) * STAGE_BYTES),
                        b, (t + 1) * 64, tid);
            CP_COMMIT();
            CP_WAIT1();
        } else {
            CP_WAIT0();
        }
        __syncthreads();   // tile t visible to all warps

        // GEMM1: S = Q @ K^T (bf16x3), Q frags from registers
        float s[8][4];
#pragma unroll
        for (int nt = 0; nt < 8; nt++)
#pragma unroll
            for (int c = 0; c < 4; c++) s[nt][c] = 0.0f;
#pragma unroll
        for (int kc = 0; kc < 4; kc++) {
#pragma unroll
            for (int np = 0; np < 4; np++) {
                const uint32_t bo = (uint32_t)(np * 16 + bRow) * ATS + bKo + kc * 32;
                uint32_t kh[4], kl[4];
                ldm_x4(kh, cbase + RKH + bo);
                ldm_x4(kl, cbase + RKL + bo);
                mma_bf16(s[2 * np],     qh[kc], kh[0], kh[1]);
                mma_bf16(s[2 * np + 1], qh[kc], kh[2], kh[3]);
                mma_bf16(s[2 * np],     qh[kc], kl[0], kl[1]);
                mma_bf16(s[2 * np + 1], qh[kc], kl[2], kl[3]);
                mma_bf16(s[2 * np],     ql[kc], kh[0], kh[1]);
                mma_bf16(s[2 * np + 1], ql[kc], kh[2], kh[3]);
            }
        }

        // Online softmax + P hi/lo pack (registers only)
        const bool maskt = (t == nkv - 1);
        uint32_t ph0[8], pl0[8], ph1[8], pl1[8];
        {   // row 0 (g): c0, c1
            const int qrow = q0 + w * 16 + g;
            if (maskt) {
#pragma unroll
                for (int nt = 0; nt < 8; nt++) {
                    const int key = k0 + nt * 8 + 2 * qd;
                    if (key > qrow)     s[nt][0] = -1e30f;
                    if (key + 1 > qrow) s[nt][1] = -1e30f;
                }
            }
            float mi = -1e30f;
#pragma unroll
            for (int nt = 0; nt < 8; nt++)
                mi = fmaxf(mi, fmaxf(s[nt][0], s[nt][1]));
            mi = fmaxf(mi, __shfl_xor_sync(0xffffffffu, mi, 1));
            mi = fmaxf(mi, __shfl_xor_sync(0xffffffffu, mi, 2));
            const float mnew = fmaxf(m0, mi);
            const float alpha = __expf(m0 - mnew);
            float rs = 0.0f;
#pragma unroll
            for (int nt = 0; nt < 8; nt++) {
                float p0 = __expf(s[nt][0] - mnew);
                float p1 = __expf(s[nt][1] - mnew);
                rs += p0 + p1;
                split_hl(p0, p1, ph0[nt], pl0[nt]);
                o[nt][0] *= alpha; o[nt][1] *= alpha;
            }
            rs += __shfl_xor_sync(0xffffffffu, rs, 1);
            rs += __shfl_xor_sync(0xffffffffu, rs, 2);
            l0 = l0 * alpha + rs;
            m0 = mnew;
        }
        {   // row 1 (g+8): c2, c3
            const int qrow = q0 + w * 16 + g + 8;
            if (maskt) {
#pragma unroll
                for (int nt = 0; nt < 8; nt++) {
                    const int key = k0 + nt * 8 + 2 * qd;
                    if (key > qrow)     s[nt][2] = -1e30f;
                    if (key + 1 > qrow) s[nt][3] = -1e30f;
                }
            }
            float mi = -1e30f;
#pragma unroll
            for (int nt = 0; nt < 8; nt++)
                mi = fmaxf(mi, fmaxf(s[nt][2], s[nt][3]));
            mi = fmaxf(mi, __shfl_xor_sync(0xffffffffu, mi, 1));
            mi = fmaxf(mi, __shfl_xor_sync(0xffffffffu, mi, 2));
            const float mnew = fmaxf(m1, mi);
            const float alpha = __expf(m1 - mnew);
            float rs = 0.0f;
#pragma unroll
            for (int nt = 0; nt < 8; nt++) {
                float p0 = __expf(s[nt][2] - mnew);
                float p1 = __expf(s[nt][3] - mnew);
                rs += p0 + p1;
                split_hl(p0, p1, ph1[nt], pl1[nt]);
                o[nt][2] *= alpha; o[nt][3] *= alpha;
            }
            rs += __shfl_xor_sync(0xffffffffu, rs, 1);
            rs += __shfl_xor_sync(0xffffffffu, rs, 2);
            l1 = l1 * alpha + rs;
            m1 = mnew;
        }

        // GEMM2: O += P @ V^T (bf16x3); A-frags direct from P registers
#pragma unroll
        for (int kc = 0; kc < 4; kc++) {
            uint32_t aH[4] = { ph0[2 * kc], ph1[2 * kc], ph0[2 * kc + 1], ph1[2 * kc + 1] };
            uint32_t aL[4] = { pl0[2 * kc], pl1[2 * kc], pl0[2 * kc + 1], pl1[2 * kc + 1] };
#pragma unroll
            for (int np = 0; np < 4; np++) {
                const uint32_t bo = (uint32_t)(np * 16 + bRow) * ATS + bKo + kc * 32;
                uint32_t vh[4], vl[4];
                ldm_x4(vh, cbase + RVH + bo);
                ldm_x4(vl, cbase + RVL + bo);
                mma_bf16(o[2 * np],     aH, vh[0], vh[1]);
                mma_bf16(o[2 * np + 1], aH, vh[2], vh[3]);
                mma_bf16(o[2 * np],     aH, vl[0], vl[1]);
                mma_bf16(o[2 * np + 1], aH, vl[2], vl[3]);
                mma_bf16(o[2 * np],     aL, vh[0], vh[1]);
                mma_bf16(o[2 * np + 1], aL, vh[2], vh[3]);
            }
        }

        __syncthreads();   // all warps done reading this stage before it's refilled
    }

    // Epilogue: write UNNORMALIZED partial O + (m, l)
    const int base = ((b * NS + split) * NJ + j) * 64;
    const int row0 = w * 16 + g;
    const int row1 = row0 + 8;
#pragma unroll
    for (int nt = 0; nt < 8; nt++) {
        const int col = nt * 8 + 2 * qd;
        *reinterpret_cast<float2*>(&g_Opart[(base + row0) * DK + col]) =
            make_float2(o[nt][0], o[nt][1]);
        *reinterpret_cast<float2*>(&g_Opart[(base + row1) * DK + col]) =
            make_float2(o[nt][2], o[nt][3]);
    }
    if (qd == 0) {
        g_ml[base + row0] = make_float2(m0, l0);
        g_ml[base + row1] = make_float2(m1, l1);
    }
}

// =====================================================================
// Kernel 3: combine partials. grid = (NJ, 4), block = 256.
// =====================================================================
__global__ __launch_bounds__(256) void combine_kernel(float* __restrict__ out)
{
    const int j = blockIdx.x, b = blockIdx.y;
    const int tid = threadIdx.x;
    const int r = tid >> 2;
    const int c0 = (tid & 3) * 16;
    const int nkv = j + 1;
    const int per = (nkv + NS - 1) / NS;
    const int nsp = (nkv + per - 1) / per;

    float mv[NS], lv[NS];
    float M = -1e30f;
    for (int s = 0; s < nsp; s++) {
        float2 ml = g_ml[((b * NS + s) * NJ + j) * 64 + r];
        mv[s] = ml.x; lv[s] = ml.y;
        M = fmaxf(M, mv[s]);
    }
    float L = 0.0f, ww[NS];
    for (int s = 0; s < nsp; s++) {
        ww[s] = __expf(mv[s] - M);
        L += ww[s] * lv[s];
    }
    const float inv = 1.0f / L;

    float4 acc[4];
#pragma unroll
    for (int q = 0; q < 4; q++) acc[q] = make_float4(0.f, 0.f, 0.f, 0.f);

    for (int s = 0; s < nsp; s++) {
        const float* Op = &g_Opart[(((b * NS + s) * NJ + j) * 64 + r) * DK + c0];
        const float ws = ww[s];
#pragma unroll
        for (int q = 0; q < 4; q++) {
            float4 v = *reinterpret_cast<const float4*>(Op + q * 4);
            acc[q].x += ws * v.x; acc[q].y += ws * v.y;
            acc[q].z += ws * v.z; acc[q].w += ws * v.w;
        }
    }

    float* op = &out[((b * S_) + j * 64 + r) * DK + c0];
#pragma unroll
    for (int q = 0; q < 4; q++) {
        float4 v = make_float4(acc[q].x * inv, acc[q].y * inv,
                               acc[q].z * inv, acc[q].w * inv);
        *reinterpret_cast<float4*>(op + q * 4) = v;
    }
}

// =====================================================================
extern "C" void kernel_launch(void* const* d_in, const int* in_sizes, int n_in,
                              void* d_out, int out_size)
{
    const float* x  = (const float*)d_in[0];
    const float* WQ = (const float*)d_in[1];
    const float* WK = (const float*)d_in[2];
    const float* WV = (const float*)d_in[3];
    float* out = (float*)d_out;

    (void)in_sizes; (void)n_in; (void)out_size;

    cudaFuncSetAttribute(proj_kernel, cudaFuncAttributeMaxDynamicSharedMemorySize, PSM_TOTAL);
    cudaFuncSetAttribute(attn_kernel, cudaFuncAttributeMaxDynamicSharedMemorySize, ATTN_SMEM);

    prep_w<<<PN, 256>>>(WQ, WK, WV);
    proj_kernel<<<128, 256, PSM_TOTAL>>>(x);
    attn_kernel<<<dim3(NJ, 4, NS), 128, ATTN_SMEM>>>();
    combine_kernel<<<dim3(NJ, 4), 256>>>(out);
}

// round 16
// speedup vs baseline: 1.2856x; 1.2108x over previous
#include <cuda_runtime.h>
#include <cuda_bf16.h>
#include <cuda_fp16.h>
#include <cstdint>

#define B_  4
#define S_  4096
#define DM  768
#define DK  64
#define NS  8          // KV splits per q-tile
#define NJ  64         // number of 64-row q-tiles per batch
#define PN  192        // proj MMA N (WQ|WK|WV)

// Scratch (device globals: no allocation allowed)
__device__ float  g_Opart[B_ * NS * NJ * 64 * DK];  // unnormalized partial O
__device__ float2 g_ml   [B_ * NS * NJ * 64];       // per-row (m, l) per split
__device__ __nv_bfloat16 g_Wbh[PN * DM];            // W^T hi  [n][k] (proj bf16x3)
__device__ __nv_bfloat16 g_Wbl[PN * DM];            // W^T lo  [n][k]
__device__ __half g_Qh[B_ * S_ * DK];               // Q hi fp16 [s][d] (x0.125)
__device__ __half g_Ql[B_ * S_ * DK];               // Q lo fp16
__device__ __half g_Kh[B_ * S_ * DK];               // K fp16 [s][d] (single)
__device__ __half g_Vh[B_ * DK * S_];               // V^T fp16 [d][s] (single)

// ---------------- legacy tensor-core / async-copy helpers (sm_80 PTX) -------
__device__ __forceinline__ uint32_t smem_u32(const void* p) {
    uint32_t a;
    asm("{ .reg .u64 t; cvta.to.shared.u64 t, %1; cvt.u32.u64 %0, t; }"
        : "=r"(a) : "l"(p));
    return a;
}
__device__ __forceinline__ void ldm_x4(uint32_t* r, uint32_t addr) {
    asm volatile("ldmatrix.sync.aligned.m8n8.x4.shared.b16 {%0,%1,%2,%3}, [%4];"
                 : "=r"(r[0]), "=r"(r[1]), "=r"(r[2]), "=r"(r[3]) : "r"(addr));
}
__device__ __forceinline__ void mma_bf16(float* d, const uint32_t* a,
                                         uint32_t b0, uint32_t b1) {
    asm volatile("mma.sync.aligned.m16n8k16.row.col.f32.bf16.bf16.f32 "
                 "{%0,%1,%2,%3}, {%4,%5,%6,%7}, {%8,%9}, {%0,%1,%2,%3};"
                 : "+f"(d[0]), "+f"(d[1]), "+f"(d[2]), "+f"(d[3])
                 : "r"(a[0]), "r"(a[1]), "r"(a[2]), "r"(a[3]), "r"(b0), "r"(b1));
}
__device__ __forceinline__ void mma_f16(float* d, const uint32_t* a,
                                        uint32_t b0, uint32_t b1) {
    asm volatile("mma.sync.aligned.m16n8k16.row.col.f32.f16.f16.f32 "
                 "{%0,%1,%2,%3}, {%4,%5,%6,%7}, {%8,%9}, {%0,%1,%2,%3};"
                 : "+f"(d[0]), "+f"(d[1]), "+f"(d[2]), "+f"(d[3])
                 : "r"(a[0]), "r"(a[1]), "r"(a[2]), "r"(a[3]), "r"(b0), "r"(b1));
}
__device__ __forceinline__ void cp16(uint32_t dst, const void* src) {
    asm volatile("cp.async.cg.shared.global [%0], [%1], 16;"
                 :: "r"(dst), "l"(src) : "memory");
}
#define CP_COMMIT() asm volatile("cp.async.commit_group;" ::: "memory")
#define CP_WAIT1()  asm volatile("cp.async.wait_group 1;" ::: "memory")
#define CP_WAIT0()  asm volatile("cp.async.wait_group 0;" ::: "memory")

__device__ __forceinline__ uint32_t bf2u(__nv_bfloat162 v) {
    return *reinterpret_cast<uint32_t*>(&v);
}
__device__ __forceinline__ void split_hl_bf(float x, float y, uint32_t& h, uint32_t& l) {
    __nv_bfloat162 hb = __floats2bfloat162_rn(x, y);
    float2 hf = __bfloat1622float2(hb);
    __nv_bfloat162 lb = __floats2bfloat162_rn(x - hf.x, y - hf.y);
    h = bf2u(hb); l = bf2u(lb);
}
__device__ __forceinline__ uint32_t h2u(__half2 v) {
    return *reinterpret_cast<uint32_t*>(&v);
}
__device__ __forceinline__ void split_hl_f16(float x, float y, uint32_t& h, uint32_t& l) {
    __half2 hb = __floats2half2_rn(x, y);
    float2 hf = __half22float2(hb);
    __half2 lb = __floats2half2_rn(x - hf.x, y - hf.y);
    h = h2u(hb); l = h2u(lb);
}

// =====================================================================
// Kernel 0: prep W — transpose + bf16 hi/lo split of [WQ|WK|WV].
// =====================================================================
__global__ __launch_bounds__(256) void prep_w(
    const float* __restrict__ WQ,
    const float* __restrict__ WK,
    const float* __restrict__ WV)
{
    const int n = blockIdx.x;
    const float* W = (n < 64) ? WQ : ((n < 128) ? WK : WV);
    const int col = n & 63;
    const int tid = threadIdx.x;
#pragma unroll
    for (int e = 0; e < 3; e++) {
        const int k = tid * 3 + e;
        float v = W[k * DK + col];
        __nv_bfloat16 h = __float2bfloat16_rn(v);
        __nv_bfloat16 l = __float2bfloat16_rn(v - __bfloat162float(h));
        g_Wbh[n * DM + k] = h;
        g_Wbl[n * DM + k] = l;
    }
}

// =====================================================================
// Kernel 1: QKV projection via mma.sync bf16x3 (fp32 accum).
// grid = 128, block = 256 (8 warps). Epilogue emits fp16: Qh/Ql [s][d],
// Kh [s][d] (single), Vh^T [d][s] (single).
// =====================================================================
#define ASM_AH 0
#define ASM_AL (128 * 144)               // 18432
#define ASM_BH (2 * 128 * 144)           // 36864
#define ASM_BL (ASM_BH + PN * 144)       // 64512
#define PSM_TOTAL (ASM_BL + PN * 144)    // 92160

__global__ __launch_bounds__(256, 1) void proj_kernel(const float* __restrict__ x)
{
    extern __shared__ char smraw[];
    const uint32_t smb = smem_u32(smraw);
    const int tid = threadIdx.x;
    const int w = tid >> 5;
    const int lane = tid & 31;
    const int row0 = blockIdx.x * 128;

    float acc[24][4];
#pragma unroll
    for (int nt = 0; nt < 24; nt++)
#pragma unroll
        for (int q = 0; q < 4; q++) acc[nt][q] = 0.0f;

    const uint32_t aOff = (uint32_t)(w * 16 + (lane & 15)) * 144 + (uint32_t)((lane >> 4) * 16);
    const uint32_t bRow = (uint32_t)((lane & 7) | ((lane & 16) >> 1));
    const uint32_t bKo  = (uint32_t)(((lane >> 3) & 1) * 16);

    for (int kc = 0; kc < DM / 64; kc++) {
        const int k0 = kc * 64;
        __syncthreads();

#pragma unroll
        for (int i = 0; i < 4; i++) {
            const int item = i * 256 + tid;
            const int r = item >> 3, gp = item & 7;
            const float* src = &x[(row0 + r) * DM + k0 + gp * 8];
            float4 a = *reinterpret_cast<const float4*>(src);
            float4 b = *reinterpret_cast<const float4*>(src + 4);
            uint4 hv, lv;
            split_hl_bf(a.x, a.y, hv.x, lv.x);
            split_hl_bf(a.z, a.w, hv.y, lv.y);
            split_hl_bf(b.x, b.y, hv.z, lv.z);
            split_hl_bf(b.z, b.w, hv.w, lv.w);
            const uint32_t off = (uint32_t)(r * 144 + gp * 16);
            *reinterpret_cast<uint4*>(smraw + ASM_AH + off) = hv;
            *reinterpret_cast<uint4*>(smraw + ASM_AL + off) = lv;
        }
#pragma unroll
        for (int i = 0; i < 6; i++) {
            const int item = i * 256 + tid;
            const int n = item >> 3, gp = item & 7;
            uint4 hv = *reinterpret_cast<const uint4*>(&g_Wbh[n * DM + k0 + gp * 8]);
            uint4 lv = *reinterpret_cast<const uint4*>(&g_Wbl[n * DM + k0 + gp * 8]);
            const uint32_t off = (uint32_t)(n * 144 + gp * 16);
            *reinterpret_cast<uint4*>(smraw + ASM_BH + off) = hv;
            *reinterpret_cast<uint4*>(smraw + ASM_BL + off) = lv;
        }
        __syncthreads();

#pragma unroll
        for (int ks = 0; ks < 4; ks++) {
            uint32_t ah[4], al[4];
            ldm_x4(ah, smb + ASM_AH + aOff + ks * 32);
            ldm_x4(al, smb + ASM_AL + aOff + ks * 32);
#pragma unroll
            for (int np = 0; np < 12; np++) {
                const uint32_t bo = (uint32_t)(np * 16 + bRow) * 144 + bKo + ks * 32;
                uint32_t bh[4], bl[4];
                ldm_x4(bh, smb + ASM_BH + bo);
                ldm_x4(bl, smb + ASM_BL + bo);
                mma_bf16(acc[2 * np],     ah, bh[0], bh[1]);
                mma_bf16(acc[2 * np + 1], ah, bh[2], bh[3]);
                mma_bf16(acc[2 * np],     ah, bl[0], bl[1]);
                mma_bf16(acc[2 * np + 1], ah, bl[2], bl[3]);
                mma_bf16(acc[2 * np],     al, bh[0], bh[1]);
                mma_bf16(acc[2 * np + 1], al, bh[2], bh[3]);
            }
        }
    }

    // Epilogue. C-frag: (row g, cols c2,c2+1) = d0,d1; row g+8 = d2,d3.
    const int g = lane >> 2;
    const int c2 = (lane & 3) * 2;
    const int r0g = row0 + w * 16 + g;
#pragma unroll
    for (int nt = 0; nt < 8; nt++) {
        const int col = nt * 8 + c2;
        uint32_t h, l;
        // Q (x0.125), fp16 hi/lo
        split_hl_f16(acc[nt][0] * 0.125f, acc[nt][1] * 0.125f, h, l);
        *reinterpret_cast<uint32_t*>(&g_Qh[r0g * DK + col]) = h;
        *reinterpret_cast<uint32_t*>(&g_Ql[r0g * DK + col]) = l;
        split_hl_f16(acc[nt][2] * 0.125f, acc[nt][3] * 0.125f, h, l);
        *reinterpret_cast<uint32_t*>(&g_Qh[(r0g + 8) * DK + col]) = h;
        *reinterpret_cast<uint32_t*>(&g_Ql[(r0g + 8) * DK + col]) = l;
        // K single fp16
        *reinterpret_cast<uint32_t*>(&g_Kh[r0g * DK + col]) =
            h2u(__floats2half2_rn(acc[nt + 8][0], acc[nt + 8][1]));
        *reinterpret_cast<uint32_t*>(&g_Kh[(r0g + 8) * DK + col]) =
            h2u(__floats2half2_rn(acc[nt + 8][2], acc[nt + 8][3]));
    }

    // V: stage fp32 [d][s] in SMEM (overlays A/B), then single fp16 to g_Vh
    __syncthreads();
    float* stage = reinterpret_cast<float*>(smraw);   // [64][136] = 34816 B
    const int srow = w * 16 + g;
#pragma unroll
    for (int nt = 16; nt < 24; nt++) {
        const int d = (nt - 16) * 8 + c2;
        stage[d * 136 + srow]           = acc[nt][0];
        stage[(d + 1) * 136 + srow]     = acc[nt][1];
        stage[d * 136 + srow + 8]       = acc[nt][2];
        stage[(d + 1) * 136 + srow + 8] = acc[nt][3];
    }
    __syncthreads();
    const int bb = row0 >> 12;
    const int s0 = row0 & (S_ - 1);
#pragma unroll
    for (int i = 0; i < 8; i++) {
        const int item = i * 256 + tid;   // 2048 items: 64 d x 32 float4
        const int d = item >> 5, s4 = item & 31;
        float4 v = *reinterpret_cast<const float4*>(&stage[d * 136 + s4 * 4]);
        uint2 hv;
        hv.x = h2u(__floats2half2_rn(v.x, v.y));
        hv.y = h2u(__floats2half2_rn(v.z, v.w));
        *reinterpret_cast<uint2*>(&g_Vh[(bb * DK + d) * S_ + s0 + s4 * 4]) = hv;
    }
}

// =====================================================================
// Kernel 2: split-KV causal flash attention, mma.sync fp16x2, cp.async
// double-buffered K/V. grid = (NJ, 4, NS), block = 128 (4 warps).
// GEMM1 = (Qh+Ql)·Kh; GEMM2 = (Ph+Pl)·Vh. Q frags hoisted to regs.
// SMEM = 2 stages x (KH,VH) x 9216B = 36.9KB -> 4 blocks/SM.
// =====================================================================
#define ATS 144
#define STAGE_BYTES (2 * 64 * ATS)       // 18432 per stage
#define RKH 0
#define RVH (64 * ATS)
#define ATTN_SMEM (2 * STAGE_BYTES)      // 36864

__device__ __forceinline__ void prefetch_kv(uint32_t base, int b, int k0, int tid)
{
#pragma unroll
    for (int i = 0; i < 4; i++) {
        const int item = i * 128 + tid;   // 512 items: 64 rows x 8 groups
        const int r = item >> 3, gp = item & 7;
        const uint32_t off = (uint32_t)(r * ATS + gp * 16);
        cp16(base + RKH + off, &g_Kh[(b * S_ + k0 + r) * DK + gp * 8]);
        cp16(base + RVH + off, &g_Vh[(b * DK + r) * S_ + k0 + gp * 8]);
    }
}

__global__ __launch_bounds__(128, 4) void attn_kernel()
{
    extern __shared__ char smraw[];
    const uint32_t smb = smem_u32(smraw);
    const int tid = threadIdx.x;
    const int w = tid >> 5;
    const int lane = tid & 31;
    const int g = lane >> 2;
    const int qd = lane & 3;
    const int b = blockIdx.y;
    const int j = blockIdx.x;
    const int split = blockIdx.z;
    const int q0 = j * 64;
    const int nkv = j + 1;
    const int per = (nkv + NS - 1) / NS;
    const int t0 = split * per;
    const int t1 = min(nkv, t0 + per);
    if (t0 >= t1) return;

    const uint32_t aOff = (uint32_t)(w * 16 + (lane & 15)) * ATS + (uint32_t)((lane >> 4) * 16);
    const uint32_t bRow = (uint32_t)((lane & 7) | ((lane & 16) >> 1));
    const uint32_t bKo  = (uint32_t)(((lane >> 3) & 1) * 16);

    // Stage Q (64x64 fp16 hi/lo) through stage-0 regions, hoist frags to regs
#pragma unroll
    for (int i = 0; i < 4; i++) {
        const int item = i * 128 + tid;
        const int r = item >> 3, gp = item & 7;
        const int src = (b * S_ + q0 + r) * DK + gp * 8;
        const uint32_t off = (uint32_t)(r * ATS + gp * 16);
        *reinterpret_cast<uint4*>(smraw + RKH + off) =
            *reinterpret_cast<const uint4*>(&g_Qh[src]);
        *reinterpret_cast<uint4*>(smraw + RVH + off) =
            *reinterpret_cast<const uint4*>(&g_Ql[src]);
    }
    __syncthreads();
    uint32_t qh[4][4], ql[4][4];
#pragma unroll
    for (int kc = 0; kc < 4; kc++) {
        ldm_x4(qh[kc], smb + RKH + aOff + kc * 32);
        ldm_x4(ql[kc], smb + RVH + aOff + kc * 32);
    }
    __syncthreads();   // Q frag loads complete before cp.async overwrites stage 0

    // Prologue prefetch: tile t0 -> stage 0
    prefetch_kv(smb, b, t0 * 64, tid);
    CP_COMMIT();

    float o[8][4];
#pragma unroll
    for (int nt = 0; nt < 8; nt++)
#pragma unroll
        for (int c = 0; c < 4; c++) o[nt][c] = 0.0f;
    float m0 = -1e30f, m1 = -1e30f, l0 = 0.0f, l1 = 0.0f;

    for (int t = t0; t < t1; t++) {
        const int k0 = t * 64;
        const uint32_t cbase = smb + (uint32_t)(((t - t0) & 1) * STAGE_BYTES);

        if (t + 1 < t1) {
            prefetch_kv(smb + (uint32_t)(((t + 1 - t0) & 1) * STAGE_BYTES),
                        b, (t + 1) * 64, tid);
            CP_COMMIT();
            CP_WAIT1();
        } else {
            CP_WAIT0();
        }
        __syncthreads();   // tile t visible to all warps

        // GEMM1: S = (Qh + Ql) @ Kh^T (fp16x2)
        float s[8][4];
#pragma unroll
        for (int nt = 0; nt < 8; nt++)
#pragma unroll
            for (int c = 0; c < 4; c++) s[nt][c] = 0.0f;
#pragma unroll
        for (int kc = 0; kc < 4; kc++) {
#pragma unroll
            for (int np = 0; np < 4; np++) {
                const uint32_t bo = (uint32_t)(np * 16 + bRow) * ATS + bKo + kc * 32;
                uint32_t kh[4];
                ldm_x4(kh, cbase + RKH + bo);
                mma_f16(s[2 * np],     qh[kc], kh[0], kh[1]);
                mma_f16(s[2 * np + 1], qh[kc], kh[2], kh[3]);
                mma_f16(s[2 * np],     ql[kc], kh[0], kh[1]);
                mma_f16(s[2 * np + 1], ql[kc], kh[2], kh[3]);
            }
        }

        // Online softmax + P hi/lo fp16 pack (registers only)
        const bool maskt = (t == nkv - 1);
        uint32_t ph0[8], pl0[8], ph1[8], pl1[8];
        {   // row 0 (g): c0, c1
            const int qrow = q0 + w * 16 + g;
            if (maskt) {
#pragma unroll
                for (int nt = 0; nt < 8; nt++) {
                    const int key = k0 + nt * 8 + 2 * qd;
                    if (key > qrow)     s[nt][0] = -1e30f;
                    if (key + 1 > qrow) s[nt][1] = -1e30f;
                }
            }
            float mi = -1e30f;
#pragma unroll
            for (int nt = 0; nt < 8; nt++)
                mi = fmaxf(mi, fmaxf(s[nt][0], s[nt][1]));
            mi = fmaxf(mi, __shfl_xor_sync(0xffffffffu, mi, 1));
            mi = fmaxf(mi, __shfl_xor_sync(0xffffffffu, mi, 2));
            const float mnew = fmaxf(m0, mi);
            const float alpha = __expf(m0 - mnew);
            float rs = 0.0f;
#pragma unroll
            for (int nt = 0; nt < 8; nt++) {
                float p0 = __expf(s[nt][0] - mnew);
                float p1 = __expf(s[nt][1] - mnew);
                rs += p0 + p1;
                split_hl_f16(p0, p1, ph0[nt], pl0[nt]);
                o[nt][0] *= alpha; o[nt][1] *= alpha;
            }
            rs += __shfl_xor_sync(0xffffffffu, rs, 1);
            rs += __shfl_xor_sync(0xffffffffu, rs, 2);
            l0 = l0 * alpha + rs;
            m0 = mnew;
        }
        {   // row 1 (g+8): c2, c3
            const int qrow = q0 + w * 16 + g + 8;
            if (maskt) {
#pragma unroll
                for (int nt = 0; nt < 8; nt++) {
                    const int key = k0 + nt * 8 + 2 * qd;
                    if (key > qrow)     s[nt][2] = -1e30f;
                    if (key + 1 > qrow) s[nt][3] = -1e30f;
                }
            }
            float mi = -1e30f;
#pragma unroll
            for (int nt = 0; nt < 8; nt++)
                mi = fmaxf(mi, fmaxf(s[nt][2], s[nt][3]));
            mi = fmaxf(mi, __shfl_xor_sync(0xffffffffu, mi, 1));
            mi = fmaxf(mi, __shfl_xor_sync(0xffffffffu, mi, 2));
            const float mnew = fmaxf(m1, mi);
            const float alpha = __expf(m1 - mnew);
            float rs = 0.0f;
#pragma unroll
            for (int nt = 0; nt < 8; nt++) {
                float p0 = __expf(s[nt][2] - mnew);
                float p1 = __expf(s[nt][3] - mnew);
                rs += p0 + p1;
                split_hl_f16(p0, p1, ph1[nt], pl1[nt]);
                o[nt][2] *= alpha; o[nt][3] *= alpha;
            }
            rs += __shfl_xor_sync(0xffffffffu, rs, 1);
            rs += __shfl_xor_sync(0xffffffffu, rs, 2);
            l1 = l1 * alpha + rs;
            m1 = mnew;
        }

        // GEMM2: O += (Ph + Pl) @ Vh^T (fp16x2); A-frags direct from P regs
#pragma unroll
        for (int kc = 0; kc < 4; kc++) {
            uint32_t aH[4] = { ph0[2 * kc], ph1[2 * kc], ph0[2 * kc + 1], ph1[2 * kc + 1] };
            uint32_t aL[4] = { pl0[2 * kc], pl1[2 * kc], pl0[2 * kc + 1], pl1[2 * kc + 1] };
#pragma unroll
            for (int np = 0; np < 4; np++) {
                const uint32_t bo = (uint32_t)(np * 16 + bRow) * ATS + bKo + kc * 32;
                uint32_t vh[4];
                ldm_x4(vh, cbase + RVH + bo);
                mma_f16(o[2 * np],     aH, vh[0], vh[1]);
                mma_f16(o[2 * np + 1], aH, vh[2], vh[3]);
                mma_f16(o[2 * np],     aL, vh[0], vh[1]);
                mma_f16(o[2 * np + 1], aL, vh[2], vh[3]);
            }
        }

        __syncthreads();   // all warps done reading this stage before refill
    }

    // Epilogue: write UNNORMALIZED partial O + (m, l)
    const int base = ((b * NS + split) * NJ + j) * 64;
    const int row0 = w * 16 + g;
    const int row1 = row0 + 8;
#pragma unroll
    for (int nt = 0; nt < 8; nt++) {
        const int col = nt * 8 + 2 * qd;
        *reinterpret_cast<float2*>(&g_Opart[(base + row0) * DK + col]) =
            make_float2(o[nt][0], o[nt][1]);
        *reinterpret_cast<float2*>(&g_Opart[(base + row1) * DK + col]) =
            make_float2(o[nt][2], o[nt][3]);
    }
    if (qd == 0) {
        g_ml[base + row0] = make_float2(m0, l0);
        g_ml[base + row1] = make_float2(m1, l1);
    }
}

// =====================================================================
// Kernel 3: combine partials. grid = (NJ, 4), block = 256.
// =====================================================================
__global__ __launch_bounds__(256) void combine_kernel(float* __restrict__ out)
{
    const int j = blockIdx.x, b = blockIdx.y;
    const int tid = threadIdx.x;
    const int r = tid >> 2;
    const int c0 = (tid & 3) * 16;
    const int nkv = j + 1;
    const int per = (nkv + NS - 1) / NS;
    const int nsp = (nkv + per - 1) / per;

    float mv[NS], lv[NS];
    float M = -1e30f;
    for (int s = 0; s < nsp; s++) {
        float2 ml = g_ml[((b * NS + s) * NJ + j) * 64 + r];
        mv[s] = ml.x; lv[s] = ml.y;
        M = fmaxf(M, mv[s]);
    }
    float L = 0.0f, ww[NS];
    for (int s = 0; s < nsp; s++) {
        ww[s] = __expf(mv[s] - M);
        L += ww[s] * lv[s];
    }
    const float inv = 1.0f / L;

    float4 acc[4];
#pragma unroll
    for (int q = 0; q < 4; q++) acc[q] = make_float4(0.f, 0.f, 0.f, 0.f);

    for (int s = 0; s < nsp; s++) {
        const float* Op = &g_Opart[(((b * NS + s) * NJ + j) * 64 + r) * DK + c0];
        const float ws = ww[s];
#pragma unroll
        for (int q = 0; q < 4; q++) {
            float4 v = *reinterpret_cast<const float4*>(Op + q * 4);
            acc[q].x += ws * v.x; acc[q].y += ws * v.y;
            acc[q].z += ws * v.z; acc[q].w += ws * v.w;
        }
    }

    float* op = &out[((b * S_) + j * 64 + r) * DK + c0];
#pragma unroll
    for (int q = 0; q < 4; q++) {
        float4 v = make_float4(acc[q].x * inv, acc[q].y * inv,
                               acc[q].z * inv, acc[q].w * inv);
        *reinterpret_cast<float4*>(op + q * 4) = v;
    }
}

// =====================================================================
extern "C" void kernel_launch(void* const* d_in, const int* in_sizes, int n_in,
                              void* d_out, int out_size)
{
    const float* x  = (const float*)d_in[0];
    const float* WQ = (const float*)d_in[1];
    const float* WK = (const float*)d_in[2];
    const float* WV = (const float*)d_in[3];
    float* out = (float*)d_out;

    (void)in_sizes; (void)n_in; (void)out_size;

    cudaFuncSetAttribute(proj_kernel, cudaFuncAttributeMaxDynamicSharedMemorySize, PSM_TOTAL);
    cudaFuncSetAttribute(attn_kernel, cudaFuncAttributeMaxDynamicSharedMemorySize, ATTN_SMEM);

    prep_w<<<PN, 256>>>(WQ, WK, WV);
    proj_kernel<<<128, 256, PSM_TOTAL>>>(x);
    attn_kernel<<<dim3(NJ, 4, NS), 128, ATTN_SMEM>>>();
    combine_kernel<<<dim3(NJ, 4), 256>>>(out);
}

// round 17
// speedup vs baseline: 1.4102x; 1.0969x over previous
#include <cuda_runtime.h>
#include <cuda_fp16.h>
#include <cstdint>

#define B_  4
#define S_  4096
#define DM  768
#define DK  64
#define NS  8          // KV splits per q-tile
#define NJ  64         // number of 64-row q-tiles per batch
#define PN  192        // proj MMA N (WQ|WK|WV)

// Scratch (device globals: no allocation allowed)
__device__ float  g_Opart[B_ * NS * NJ * 64 * DK];  // unnormalized partial O
__device__ float2 g_ml   [B_ * NS * NJ * 64];       // per-row (m, l) per split
__device__ __half g_Wh[PN * DM];                    // W^T fp16 [n][k] (single)
__device__ __half g_Qh[B_ * S_ * DK];               // Q hi fp16 [s][d] (x0.125)
__device__ __half g_Ql[B_ * S_ * DK];               // Q lo fp16
__device__ __half g_Kh[B_ * S_ * DK];               // K fp16 [s][d] (single)
__device__ __half g_Vh[B_ * DK * S_];               // V^T fp16 [d][s] (single)

// ---------------- legacy tensor-core / async-copy helpers (sm_80 PTX) -------
__device__ __forceinline__ uint32_t smem_u32(const void* p) {
    uint32_t a;
    asm("{ .reg .u64 t; cvta.to.shared.u64 t, %1; cvt.u32.u64 %0, t; }"
        : "=r"(a) : "l"(p));
    return a;
}
__device__ __forceinline__ void ldm_x4(uint32_t* r, uint32_t addr) {
    asm volatile("ldmatrix.sync.aligned.m8n8.x4.shared.b16 {%0,%1,%2,%3}, [%4];"
                 : "=r"(r[0]), "=r"(r[1]), "=r"(r[2]), "=r"(r[3]) : "r"(addr));
}
__device__ __forceinline__ void mma_f16(float* d, const uint32_t* a,
                                        uint32_t b0, uint32_t b1) {
    asm volatile("mma.sync.aligned.m16n8k16.row.col.f32.f16.f16.f32 "
                 "{%0,%1,%2,%3}, {%4,%5,%6,%7}, {%8,%9}, {%0,%1,%2,%3};"
                 : "+f"(d[0]), "+f"(d[1]), "+f"(d[2]), "+f"(d[3])
                 : "r"(a[0]), "r"(a[1]), "r"(a[2]), "r"(a[3]), "r"(b0), "r"(b1));
}
__device__ __forceinline__ void cp16(uint32_t dst, const void* src) {
    asm volatile("cp.async.cg.shared.global [%0], [%1], 16;"
                 :: "r"(dst), "l"(src) : "memory");
}
#define CP_COMMIT() asm volatile("cp.async.commit_group;" ::: "memory")
#define CP_WAIT1()  asm volatile("cp.async.wait_group 1;" ::: "memory")
#define CP_WAIT0()  asm volatile("cp.async.wait_group 0;" ::: "memory")

__device__ __forceinline__ uint32_t h2u(__half2 v) {
    return *reinterpret_cast<uint32_t*>(&v);
}
__device__ __forceinline__ void split_hl_f16(float x, float y, uint32_t& h, uint32_t& l) {
    __half2 hb = __floats2half2_rn(x, y);
    float2 hf = __half22float2(hb);
    __half2 lb = __floats2half2_rn(x - hf.x, y - hf.y);
    h = h2u(hb); l = h2u(lb);
}

// =====================================================================
// Kernel 0: prep W — transpose + single-fp16 cast of [WQ|WK|WV].
// =====================================================================
__global__ __launch_bounds__(256) void prep_w(
    const float* __restrict__ WQ,
    const float* __restrict__ WK,
    const float* __restrict__ WV)
{
    const int n = blockIdx.x;
    const float* W = (n < 64) ? WQ : ((n < 128) ? WK : WV);
    const int col = n & 63;
    const int tid = threadIdx.x;
#pragma unroll
    for (int e = 0; e < 3; e++) {
        const int k = tid * 3 + e;
        g_Wh[n * DM + k] = __float2half_rn(W[k * DK + col]);
    }
}

// =====================================================================
// Kernel 1: QKV projection via mma.sync fp16x2 (fp32 accum).
// grid = 128, block = 256 (8 warps). A = x split fp16 hi/lo; W single
// fp16. Epilogue emits fp16: Qh/Ql [s][d], Kh [s][d], Vh^T [d][s].
// SMEM 64.5 KB.
// =====================================================================
#define ASM_AH 0
#define ASM_AL (128 * 144)               // 18432
#define ASM_WH (2 * 128 * 144)           // 36864
#define PSM_TOTAL (ASM_WH + PN * 144)    // 64512

__global__ __launch_bounds__(256, 1) void proj_kernel(const float* __restrict__ x)
{
    extern __shared__ char smraw[];
    const uint32_t smb = smem_u32(smraw);
    const int tid = threadIdx.x;
    const int w = tid >> 5;
    const int lane = tid & 31;
    const int row0 = blockIdx.x * 128;

    float acc[24][4];
#pragma unroll
    for (int nt = 0; nt < 24; nt++)
#pragma unroll
        for (int q = 0; q < 4; q++) acc[nt][q] = 0.0f;

    const uint32_t aOff = (uint32_t)(w * 16 + (lane & 15)) * 144 + (uint32_t)((lane >> 4) * 16);
    const uint32_t bRow = (uint32_t)((lane & 7) | ((lane & 16) >> 1));
    const uint32_t bKo  = (uint32_t)(((lane >> 3) & 1) * 16);

    for (int kc = 0; kc < DM / 64; kc++) {
        const int k0 = kc * 64;
        __syncthreads();

        // A chunk: x[row0..+127][k0..+63] -> fp16 hi/lo
#pragma unroll
        for (int i = 0; i < 4; i++) {
            const int item = i * 256 + tid;      // 1024 items: 128 rows x 8 groups
            const int r = item >> 3, gp = item & 7;
            const float* src = &x[(row0 + r) * DM + k0 + gp * 8];
            float4 a = *reinterpret_cast<const float4*>(src);
            float4 b = *reinterpret_cast<const float4*>(src + 4);
            uint4 hv, lv;
            split_hl_f16(a.x, a.y, hv.x, lv.x);
            split_hl_f16(a.z, a.w, hv.y, lv.y);
            split_hl_f16(b.x, b.y, hv.z, lv.z);
            split_hl_f16(b.z, b.w, hv.w, lv.w);
            const uint32_t off = (uint32_t)(r * 144 + gp * 16);
            *reinterpret_cast<uint4*>(smraw + ASM_AH + off) = hv;
            *reinterpret_cast<uint4*>(smraw + ASM_AL + off) = lv;
        }
        // W chunk copy (single fp16)
#pragma unroll
        for (int i = 0; i < 6; i++) {
            const int item = i * 256 + tid;      // 1536 items: 192 rows x 8 groups
            const int n = item >> 3, gp = item & 7;
            uint4 hv = *reinterpret_cast<const uint4*>(&g_Wh[n * DM + k0 + gp * 8]);
            *reinterpret_cast<uint4*>(smraw + ASM_WH + (uint32_t)(n * 144 + gp * 16)) = hv;
        }
        __syncthreads();

#pragma unroll
        for (int ks = 0; ks < 4; ks++) {
            uint32_t ah[4], al[4];
            ldm_x4(ah, smb + ASM_AH + aOff + ks * 32);
            ldm_x4(al, smb + ASM_AL + aOff + ks * 32);
#pragma unroll
            for (int np = 0; np < 12; np++) {
                const uint32_t bo = (uint32_t)(np * 16 + bRow) * 144 + bKo + ks * 32;
                uint32_t bh[4];
                ldm_x4(bh, smb + ASM_WH + bo);
                mma_f16(acc[2 * np],     ah, bh[0], bh[1]);
                mma_f16(acc[2 * np + 1], ah, bh[2], bh[3]);
                mma_f16(acc[2 * np],     al, bh[0], bh[1]);
                mma_f16(acc[2 * np + 1], al, bh[2], bh[3]);
            }
        }
    }

    // Epilogue. C-frag: (row g, cols c2,c2+1) = d0,d1; row g+8 = d2,d3.
    const int g = lane >> 2;
    const int c2 = (lane & 3) * 2;
    const int r0g = row0 + w * 16 + g;
#pragma unroll
    for (int nt = 0; nt < 8; nt++) {
        const int col = nt * 8 + c2;
        uint32_t h, l;
        // Q (x0.125), fp16 hi/lo
        split_hl_f16(acc[nt][0] * 0.125f, acc[nt][1] * 0.125f, h, l);
        *reinterpret_cast<uint32_t*>(&g_Qh[r0g * DK + col]) = h;
        *reinterpret_cast<uint32_t*>(&g_Ql[r0g * DK + col]) = l;
        split_hl_f16(acc[nt][2] * 0.125f, acc[nt][3] * 0.125f, h, l);
        *reinterpret_cast<uint32_t*>(&g_Qh[(r0g + 8) * DK + col]) = h;
        *reinterpret_cast<uint32_t*>(&g_Ql[(r0g + 8) * DK + col]) = l;
        // K single fp16
        *reinterpret_cast<uint32_t*>(&g_Kh[r0g * DK + col]) =
            h2u(__floats2half2_rn(acc[nt + 8][0], acc[nt + 8][1]));
        *reinterpret_cast<uint32_t*>(&g_Kh[(r0g + 8) * DK + col]) =
            h2u(__floats2half2_rn(acc[nt + 8][2], acc[nt + 8][3]));
    }

    // V: stage fp32 [d][s] in SMEM (overlays A/W), then single fp16 to g_Vh
    __syncthreads();
    float* stage = reinterpret_cast<float*>(smraw);   // [64][136] = 34816 B
    const int srow = w * 16 + g;
#pragma unroll
    for (int nt = 16; nt < 24; nt++) {
        const int d = (nt - 16) * 8 + c2;
        stage[d * 136 + srow]           = acc[nt][0];
        stage[(d + 1) * 136 + srow]     = acc[nt][1];
        stage[d * 136 + srow + 8]       = acc[nt][2];
        stage[(d + 1) * 136 + srow + 8] = acc[nt][3];
    }
    __syncthreads();
    const int bb = row0 >> 12;
    const int s0 = row0 & (S_ - 1);
#pragma unroll
    for (int i = 0; i < 8; i++) {
        const int item = i * 256 + tid;   // 2048 items: 64 d x 32 float4
        const int d = item >> 5, s4 = item & 31;
        float4 v = *reinterpret_cast<const float4*>(&stage[d * 136 + s4 * 4]);
        uint2 hv;
        hv.x = h2u(__floats2half2_rn(v.x, v.y));
        hv.y = h2u(__floats2half2_rn(v.z, v.w));
        *reinterpret_cast<uint2*>(&g_Vh[(bb * DK + d) * S_ + s0 + s4 * 4]) = hv;
    }
}

// =====================================================================
// Kernel 2: split-KV causal flash attention, mma.sync fp16x2, cp.async
// double-buffered K/V. grid = (NJ, 4, NS), block = 128 (4 warps).
// GEMM1 = (Qh+Ql)·Kh; GEMM2 = (Ph+Pl)·Vh. Q frags hoisted to regs.
// SMEM = 2 stages x (KH,VH) x 9216B = 36.9KB -> 4 blocks/SM.
// (R16 winner, unchanged.)
// =====================================================================
#define ATS 144
#define STAGE_BYTES (2 * 64 * ATS)       // 18432 per stage
#define RKH 0
#define RVH (64 * ATS)
#define ATTN_SMEM (2 * STAGE_BYTES)      // 36864

__device__ __forceinline__ void prefetch_kv(uint32_t base, int b, int k0, int tid)
{
#pragma unroll
    for (int i = 0; i < 4; i++) {
        const int item = i * 128 + tid;   // 512 items: 64 rows x 8 groups
        const int r = item >> 3, gp = item & 7;
        const uint32_t off = (uint32_t)(r * ATS + gp * 16);
        cp16(base + RKH + off, &g_Kh[(b * S_ + k0 + r) * DK + gp * 8]);
        cp16(base + RVH + off, &g_Vh[(b * DK + r) * S_ + k0 + gp * 8]);
    }
}

__global__ __launch_bounds__(128, 4) void attn_kernel()
{
    extern __shared__ char smraw[];
    const uint32_t smb = smem_u32(smraw);
    const int tid = threadIdx.x;
    const int w = tid >> 5;
    const int lane = tid & 31;
    const int g = lane >> 2;
    const int qd = lane & 3;
    const int b = blockIdx.y;
    const int j = blockIdx.x;
    const int split = blockIdx.z;
    const int q0 = j * 64;
    const int nkv = j + 1;
    const int per = (nkv + NS - 1) / NS;
    const int t0 = split * per;
    const int t1 = min(nkv, t0 + per);
    if (t0 >= t1) return;

    const uint32_t aOff = (uint32_t)(w * 16 + (lane & 15)) * ATS + (uint32_t)((lane >> 4) * 16);
    const uint32_t bRow = (uint32_t)((lane & 7) | ((lane & 16) >> 1));
    const uint32_t bKo  = (uint32_t)(((lane >> 3) & 1) * 16);

    // Stage Q (64x64 fp16 hi/lo) through stage-0 regions, hoist frags to regs
#pragma unroll
    for (int i = 0; i < 4; i++) {
        const int item = i * 128 + tid;
        const int r = item >> 3, gp = item & 7;
        const int src = (b * S_ + q0 + r) * DK + gp * 8;
        const uint32_t off = (uint32_t)(r * ATS + gp * 16);
        *reinterpret_cast<uint4*>(smraw + RKH + off) =
            *reinterpret_cast<const uint4*>(&g_Qh[src]);
        *reinterpret_cast<uint4*>(smraw + RVH + off) =
            *reinterpret_cast<const uint4*>(&g_Ql[src]);
    }
    __syncthreads();
    uint32_t qh[4][4], ql[4][4];
#pragma unroll
    for (int kc = 0; kc < 4; kc++) {
        ldm_x4(qh[kc], smb + RKH + aOff + kc * 32);
        ldm_x4(ql[kc], smb + RVH + aOff + kc * 32);
    }
    __syncthreads();   // Q frag loads complete before cp.async overwrites stage 0

    // Prologue prefetch: tile t0 -> stage 0
    prefetch_kv(smb, b, t0 * 64, tid);
    CP_COMMIT();

    float o[8][4];
#pragma unroll
    for (int nt = 0; nt < 8; nt++)
#pragma unroll
        for (int c = 0; c < 4; c++) o[nt][c] = 0.0f;
    float m0 = -1e30f, m1 = -1e30f, l0 = 0.0f, l1 = 0.0f;

    for (int t = t0; t < t1; t++) {
        const int k0 = t * 64;
        const uint32_t cbase = smb + (uint32_t)(((t - t0) & 1) * STAGE_BYTES);

        if (t + 1 < t1) {
            prefetch_kv(smb + (uint32_t)(((t + 1 - t0) & 1) * STAGE_BYTES),
                        b, (t + 1) * 64, tid);
            CP_COMMIT();
            CP_WAIT1();
        } else {
            CP_WAIT0();
        }
        __syncthreads();   // tile t visible to all warps

        // GEMM1: S = (Qh + Ql) @ Kh^T (fp16x2)
        float s[8][4];
#pragma unroll
        for (int nt = 0; nt < 8; nt++)
#pragma unroll
            for (int c = 0; c < 4; c++) s[nt][c] = 0.0f;
#pragma unroll
        for (int kc = 0; kc < 4; kc++) {
#pragma unroll
            for (int np = 0; np < 4; np++) {
                const uint32_t bo = (uint32_t)(np * 16 + bRow) * ATS + bKo + kc * 32;
                uint32_t kh[4];
                ldm_x4(kh, cbase + RKH + bo);
                mma_f16(s[2 * np],     qh[kc], kh[0], kh[1]);
                mma_f16(s[2 * np + 1], qh[kc], kh[2], kh[3]);
                mma_f16(s[2 * np],     ql[kc], kh[0], kh[1]);
                mma_f16(s[2 * np + 1], ql[kc], kh[2], kh[3]);
            }
        }

        // Online softmax + P hi/lo fp16 pack (registers only)
        const bool maskt = (t == nkv - 1);
        uint32_t ph0[8], pl0[8], ph1[8], pl1[8];
        {   // row 0 (g): c0, c1
            const int qrow = q0 + w * 16 + g;
            if (maskt) {
#pragma unroll
                for (int nt = 0; nt < 8; nt++) {
                    const int key = k0 + nt * 8 + 2 * qd;
                    if (key > qrow)     s[nt][0] = -1e30f;
                    if (key + 1 > qrow) s[nt][1] = -1e30f;
                }
            }
            float mi = -1e30f;
#pragma unroll
            for (int nt = 0; nt < 8; nt++)
                mi = fmaxf(mi, fmaxf(s[nt][0], s[nt][1]));
            mi = fmaxf(mi, __shfl_xor_sync(0xffffffffu, mi, 1));
            mi = fmaxf(mi, __shfl_xor_sync(0xffffffffu, mi, 2));
            const float mnew = fmaxf(m0, mi);
            const float alpha = __expf(m0 - mnew);
            float rs = 0.0f;
#pragma unroll
            for (int nt = 0; nt < 8; nt++) {
                float p0 = __expf(s[nt][0] - mnew);
                float p1 = __expf(s[nt][1] - mnew);
                rs += p0 + p1;
                split_hl_f16(p0, p1, ph0[nt], pl0[nt]);
                o[nt][0] *= alpha; o[nt][1] *= alpha;
            }
            rs += __shfl_xor_sync(0xffffffffu, rs, 1);
            rs += __shfl_xor_sync(0xffffffffu, rs, 2);
            l0 = l0 * alpha + rs;
            m0 = mnew;
        }
        {   // row 1 (g+8): c2, c3
            const int qrow = q0 + w * 16 + g + 8;
            if (maskt) {
#pragma unroll
                for (int nt = 0; nt < 8; nt++) {
                    const int key = k0 + nt * 8 + 2 * qd;
                    if (key > qrow)     s[nt][2] = -1e30f;
                    if (key + 1 > qrow) s[nt][3] = -1e30f;
                }
            }
            float mi = -1e30f;
#pragma unroll
            for (int nt = 0; nt < 8; nt++)
                mi = fmaxf(mi, fmaxf(s[nt][2], s[nt][3]));
            mi = fmaxf(mi, __shfl_xor_sync(0xffffffffu, mi, 1));
            mi = fmaxf(mi, __shfl_xor_sync(0xffffffffu, mi, 2));
            const float mnew = fmaxf(m1, mi);
            const float alpha = __expf(m1 - mnew);
            float rs = 0.0f;
#pragma unroll
            for (int nt = 0; nt < 8; nt++) {
                float p0 = __expf(s[nt][2] - mnew);
                float p1 = __expf(s[nt][3] - mnew);
                rs += p0 + p1;
                split_hl_f16(p0, p1, ph1[nt], pl1[nt]);
                o[nt][2] *= alpha; o[nt][3] *= alpha;
            }
            rs += __shfl_xor_sync(0xffffffffu, rs, 1);
            rs += __shfl_xor_sync(0xffffffffu, rs, 2);
            l1 = l1 * alpha + rs;
            m1 = mnew;
        }

        // GEMM2: O += (Ph + Pl) @ Vh^T (fp16x2); A-frags direct from P regs
#pragma unroll
        for (int kc = 0; kc < 4; kc++) {
            uint32_t aH[4] = { ph0[2 * kc], ph1[2 * kc], ph0[2 * kc + 1], ph1[2 * kc + 1] };
            uint32_t aL[4] = { pl0[2 * kc], pl1[2 * kc], pl0[2 * kc + 1], pl1[2 * kc + 1] };
#pragma unroll
            for (int np = 0; np < 4; np++) {
                const uint32_t bo = (uint32_t)(np * 16 + bRow) * ATS + bKo + kc * 32;
                uint32_t vh[4];
                ldm_x4(vh, cbase + RVH + bo);
                mma_f16(o[2 * np],     aH, vh[0], vh[1]);
                mma_f16(o[2 * np + 1], aH, vh[2], vh[3]);
                mma_f16(o[2 * np],     aL, vh[0], vh[1]);
                mma_f16(o[2 * np + 1], aL, vh[2], vh[3]);
            }
        }

        __syncthreads();   // all warps done reading this stage before refill
    }

    // Epilogue: write UNNORMALIZED partial O + (m, l)
    const int base = ((b * NS + split) * NJ + j) * 64;
    const int row0 = w * 16 + g;
    const int row1 = row0 + 8;
#pragma unroll
    for (int nt = 0; nt < 8; nt++) {
        const int col = nt * 8 + 2 * qd;
        *reinterpret_cast<float2*>(&g_Opart[(base + row0) * DK + col]) =
            make_float2(o[nt][0], o[nt][1]);
        *reinterpret_cast<float2*>(&g_Opart[(base + row1) * DK + col]) =
            make_float2(o[nt][2], o[nt][3]);
    }
    if (qd == 0) {
        g_ml[base + row0] = make_float2(m0, l0);
        g_ml[base + row1] = make_float2(m1, l1);
    }
}

// =====================================================================
// Kernel 3: combine partials. grid = (NJ, 4), block = 256.
// =====================================================================
__global__ __launch_bounds__(256) void combine_kernel(float* __restrict__ out)
{
    const int j = blockIdx.x, b = blockIdx.y;
    const int tid = threadIdx.x;
    const int r = tid >> 2;
    const int c0 = (tid & 3) * 16;
    const int nkv = j + 1;
    const int per = (nkv + NS - 1) / NS;
    const int nsp = (nkv + per - 1) / per;

    float mv[NS], lv[NS];
    float M = -1e30f;
    for (int s = 0; s < nsp; s++) {
        float2 ml = g_ml[((b * NS + s) * NJ + j) * 64 + r];
        mv[s] = ml.x; lv[s] = ml.y;
        M = fmaxf(M, mv[s]);
    }
    float L = 0.0f, ww[NS];
    for (int s = 0; s < nsp; s++) {
        ww[s] = __expf(mv[s] - M);
        L += ww[s] * lv[s];
    }
    const float inv = 1.0f / L;

    float4 acc[4];
#pragma unroll
    for (int q = 0; q < 4; q++) acc[q] = make_float4(0.f, 0.f, 0.f, 0.f);

    for (int s = 0; s < nsp; s++) {
        const float* Op = &g_Opart[(((b * NS + s) * NJ + j) * 64 + r) * DK + c0];
        const float ws = ww[s];
#pragma unroll
        for (int q = 0; q < 4; q++) {
            float4 v = *reinterpret_cast<const float4*>(Op + q * 4);
            acc[q].x += ws * v.x; acc[q].y += ws * v.y;
            acc[q].z += ws * v.z; acc[q].w += ws * v.w;
        }
    }

    float* op = &out[((b * S_) + j * 64 + r) * DK + c0];
#pragma unroll
    for (int q = 0; q < 4; q++) {
        float4 v = make_float4(acc[q].x * inv, acc[q].y * inv,
                               acc[q].z * inv, acc[q].w * inv);
        *reinterpret_cast<float4*>(op + q * 4) = v;
    }
}

// =====================================================================
extern "C" void kernel_launch(void* const* d_in, const int* in_sizes, int n_in,
                              void* d_out, int out_size)
{
    const float* x  = (const float*)d_in[0];
    const float* WQ = (const float*)d_in[1];
    const float* WK = (const float*)d_in[2];
    const float* WV = (const float*)d_in[3];
    float* out = (float*)d_out;

    (void)in_sizes; (void)n_in; (void)out_size;

    cudaFuncSetAttribute(proj_kernel, cudaFuncAttributeMaxDynamicSharedMemorySize, PSM_TOTAL);
    cudaFuncSetAttribute(attn_kernel, cudaFuncAttributeMaxDynamicSharedMemorySize, ATTN_SMEM);

    prep_w<<<PN, 256>>>(WQ, WK, WV);
    proj_kernel<<<128, 256, PSM_TOTAL>>>(x);
    attn_kernel<<<dim3(NJ, 4, NS), 128, ATTN_SMEM>>>();
    combine_kernel<<<dim3(NJ, 4), 256>>>(out);
}